// round 2
// baseline (speedup 1.0000x reference)
#include <cuda_runtime.h>
#include <cuda_bf16.h>

#define MAXN 6144
#define F 128
#define G 48
#define TA 16        // atoms per block in MLP kernel
#define KE_CONST 14.3996f

// ---------------- scratch (no allocations allowed) ----------------
__device__ float  g_q[MAXN];
__device__ float  g_sc6[MAXN];   // sqrt(c6)
__device__ float  g_r3[MAXN];    // r_vdw^3
__device__ float  g_qsum[G];
__device__ int    g_cnt[G];
__device__ int    g_start[G];
__device__ float  g_qmean[G];
__device__ double g_partial[MAXN];

__device__ __forceinline__ float softplusf(float x) {
    // log1p(exp(x)) stable
    return fmaxf(x, 0.0f) + log1pf(expf(-fabsf(x)));
}

__device__ __forceinline__ float siluf(float x) {
    return x / (1.0f + expf(-x));
}

// ---------------- K0: zero per-graph accumulators ----------------
__global__ void zero_kernel() {
    int t = threadIdx.x;
    if (t < G) { g_qsum[t] = 0.0f; g_cnt[t] = 0; }
}

// ---------------- K1: per-atom MLPs (both heads), 16 atoms/block ----------------
// thread j (0..127) owns hidden unit j of both heads.
__global__ __launch_bounds__(128) void mlp_kernel(
    const float* __restrict__ h0,
    const float* __restrict__ qW1, const float* __restrict__ qb1,
    const float* __restrict__ qW2,
    const float* __restrict__ vW1, const float* __restrict__ vb1,
    const float* __restrict__ vW2, const float* __restrict__ vb2,
    const int*   __restrict__ batch)
{
    // smem layout: sh0[k*20 + a]  (stride 20 floats: 16B-aligned float4 groups, spread banks)
    __shared__ float sh0[F * 20];
    __shared__ float red[4][3];

    const int base = blockIdx.x * TA;
    const int j = threadIdx.x;
    const int lane = j & 31, warp = j >> 5;

    // load h0 tile transposed into smem
    for (int idx = j; idx < TA * F; idx += 128) {
        int a = idx >> 7;          // atom within tile
        int k = idx & (F - 1);     // feature
        sh0[k * 20 + a] = h0[(base + a) * F + k];
    }
    __syncthreads();

    float accq[TA], accv[TA];
#pragma unroll
    for (int a = 0; a < TA; a++) { accq[a] = 0.0f; accv[a] = 0.0f; }

#pragma unroll 4
    for (int k = 0; k < F; k++) {
        float wq = __ldg(&qW1[k * F + j]);
        float wv = __ldg(&vW1[k * F + j]);
        const float4* p = reinterpret_cast<const float4*>(&sh0[k * 20]);
        float4 xa = p[0], xb = p[1], xc = p[2], xd = p[3];
        float xs[16] = { xa.x, xa.y, xa.z, xa.w,
                         xb.x, xb.y, xb.z, xb.w,
                         xc.x, xc.y, xc.z, xc.w,
                         xd.x, xd.y, xd.z, xd.w };
#pragma unroll
        for (int a = 0; a < TA; a++) {
            accq[a] = fmaf(xs[a], wq, accq[a]);
            accv[a] = fmaf(xs[a], wv, accv[a]);
        }
    }

    const float bq  = qb1[j];
    const float w2q = qW2[j];
    const float bv  = vb1[j];
    const float w2v0 = vW2[2 * j + 0];
    const float w2v1 = vW2[2 * j + 1];

    for (int a = 0; a < TA; a++) {
        float sq = siluf(accq[a] + bq);
        float qc = sq * w2q;
        float sv = siluf(accv[a] + bv);
        float v0 = sv * w2v0;
        float v1 = sv * w2v1;
#pragma unroll
        for (int o = 16; o > 0; o >>= 1) {
            qc += __shfl_down_sync(0xFFFFFFFFu, qc, o);
            v0 += __shfl_down_sync(0xFFFFFFFFu, v0, o);
            v1 += __shfl_down_sync(0xFFFFFFFFu, v1, o);
        }
        if (lane == 0) { red[warp][0] = qc; red[warp][1] = v0; red[warp][2] = v1; }
        __syncthreads();
        if (j == 0) {
            float qv = red[0][0] + red[1][0] + red[2][0] + red[3][0];
            float p0 = red[0][1] + red[1][1] + red[2][1] + red[3][1] + vb2[0];
            float p1 = red[0][2] + red[1][2] + red[2][2] + red[3][2] + vb2[1];
            int i = base + a;
            g_q[i] = qv;
            int b = batch[i];
            atomicAdd(&g_qsum[b], qv);
            atomicAdd(&g_cnt[b], 1);
            float c6 = softplusf(p0);
            float rv = softplusf(p1);
            g_sc6[i] = sqrtf(c6);
            g_r3[i]  = rv * rv * rv;
        }
        __syncthreads();
    }
}

// ---------------- K2: segment starts + per-graph mean ----------------
__global__ void seg_kernel() {
    if (threadIdx.x == 0) {
        int s = 0;
        for (int g = 0; g < G; g++) {
            g_start[g] = s;
            s += g_cnt[g];
            g_qmean[g] = g_qsum[g] / fmaxf((float)g_cnt[g], 1.0f);
        }
    }
}

// ---------------- K3: pairwise energies (one block per atom i) ----------------
__global__ __launch_bounds__(128) void pair_kernel(
    const float* __restrict__ pos,
    const int*   __restrict__ batch,
    const float* __restrict__ sigma)
{
    const int i = blockIdx.x;
    const int g = batch[i];
    const int s = g_start[g];
    const int c = g_cnt[g];
    const float qm = g_qmean[g];

    const float qi   = g_q[i] - qm;
    const float px   = pos[3 * i + 0];
    const float py   = pos[3 * i + 1];
    const float pz   = pos[3 * i + 2];
    const float sc6i = g_sc6[i];
    const float r3i  = g_r3[i];
    const float invs = 1.0f / (1.41421356f * sigma[0]);

    float eel = 0.0f, evd = 0.0f;
    for (int j = s + (int)threadIdx.x; j < s + c; j += blockDim.x) {
        if (j == i) continue;
        float dx = px - pos[3 * j + 0];
        float dy = py - pos[3 * j + 1];
        float dz = pz - pos[3 * j + 2];
        float dsq  = dx * dx + dy * dy + dz * dz;
        float dist = sqrtf(dsq + 1e-8f);
        float qj = g_q[j] - qm;
        eel += qi * qj * (1.0f / (dist + 1e-8f)) * erff(dist * invs);
        float damp = dsq * dsq * dsq + r3i * g_r3[j];
        evd -= (sc6i * g_sc6[j]) / (damp + 1e-8f);
    }

    float tot = KE_CONST * eel + evd;
#pragma unroll
    for (int o = 16; o > 0; o >>= 1)
        tot += __shfl_down_sync(0xFFFFFFFFu, tot, o);

    __shared__ float sred[4];
    int lane = threadIdx.x & 31, warp = threadIdx.x >> 5;
    if (lane == 0) sred[warp] = tot;
    __syncthreads();
    if (threadIdx.x == 0) {
        float t = sred[0] + sred[1] + sred[2] + sred[3];
        g_partial[i] = 0.5 * (double)t;
    }
}

// ---------------- K4: final reduction -> scalar out ----------------
__global__ void finish_kernel(float* __restrict__ out, int N) {
    __shared__ double sred[8];
    double acc = 0.0;
    for (int idx = threadIdx.x; idx < N; idx += blockDim.x)
        acc += g_partial[idx];
#pragma unroll
    for (int o = 16; o > 0; o >>= 1)
        acc += __shfl_down_sync(0xFFFFFFFFu, acc, o);
    int lane = threadIdx.x & 31, warp = threadIdx.x >> 5;
    if (lane == 0) sred[warp] = acc;
    __syncthreads();
    if (threadIdx.x == 0) {
        double t = 0.0;
        int nw = (blockDim.x + 31) >> 5;
        for (int w = 0; w < nw; w++) t += sred[w];
        out[0] = (float)t;   // LONG_RANGE_SCALE = 1.0
    }
}

// ---------------- launch ----------------
extern "C" void kernel_launch(void* const* d_in, const int* in_sizes, int n_in,
                              void* d_out, int out_size) {
    const float* h0    = (const float*)d_in[0];
    // d_in[1] = h1 (unused on this path)
    const float* pos   = (const float*)d_in[2];
    const float* qW1   = (const float*)d_in[3];
    const float* qb1   = (const float*)d_in[4];
    const float* qW2   = (const float*)d_in[5];
    const float* sigma = (const float*)d_in[6];
    const float* vW1   = (const float*)d_in[7];
    const float* vb1   = (const float*)d_in[8];
    const float* vW2   = (const float*)d_in[9];
    const float* vb2   = (const float*)d_in[10];
    const int*   batch = (const int*)d_in[11];

    const int N = in_sizes[0] / F;   // 6144

    zero_kernel<<<1, 64>>>();
    mlp_kernel<<<N / TA, 128>>>(h0, qW1, qb1, qW2, vW1, vb1, vW2, vb2, batch);
    seg_kernel<<<1, 32>>>();
    pair_kernel<<<N, 128>>>(pos, batch, sigma);
    finish_kernel<<<1, 256>>>((float*)d_out, N);
}

// round 3
// speedup vs baseline: 1.0679x; 1.0679x over previous
#include <cuda_runtime.h>
#include <cuda_bf16.h>

#define MAXN 6144
#define F 128
#define G 48
#define TA 32          // atoms per MLP block
#define CHUNK 8        // weight rows staged per chunk
#define SPLIT 3        // blocks per graph in pair kernel
#define MAXC 512       // max atoms per graph (actual ~128)
#define KE_CONST 14.3996f

typedef unsigned long long u64;

// ---------------- scratch ----------------
__device__ float  g_q[MAXN];
__device__ float  g_sc6[MAXN];   // sqrt(c6)
__device__ float  g_r3[MAXN];    // r_vdw^3
__device__ float  g_qsum[G];
__device__ int    g_cnt[G];
__device__ int    g_start[G];
__device__ float  g_qmean[G];
__device__ double g_partial[G * SPLIT];

__device__ __forceinline__ float softplusf(float x) {
    return fmaxf(x, 0.0f) + log1pf(expf(-fabsf(x)));
}
__device__ __forceinline__ float siluf(float x) {
    return x / (1.0f + expf(-x));
}

// packed double-rate fp32 FMA (sm_100+): d = a*b + d on two lanes
#define FMA2(acc, w, x) asm("fma.rn.f32x2 %0, %1, %2, %0;" : "+l"(acc) : "l"(w), "l"(x))

__device__ __forceinline__ void unpack2(u64 p, float &lo, float &hi) {
    asm("mov.b64 {%0,%1}, %2;" : "=f"(lo), "=f"(hi) : "l"(p));
}

union F4U { float4 f; u64 u[2]; };

// ---------------- K0: zero per-graph accumulators ----------------
__global__ void zero_kernel() {
    int t = threadIdx.x;
    if (t < G) g_qsum[t] = 0.0f;
}

// ---------------- K1: per-atom MLPs, 32 atoms/block ----------------
// 128 threads = 32 hidden-groups (hg: 4 hidden units) x 4 atom-groups (ag: 8 atoms)
// tid = hg*4 + ag.  Weights staged through smem; packed f32x2 FMAs.
__global__ __launch_bounds__(128) void mlp_kernel(
    const float* __restrict__ h0,
    const float* __restrict__ qW1, const float* __restrict__ qb1,
    const float* __restrict__ qW2,
    const float* __restrict__ vW1, const float* __restrict__ vb1,
    const float* __restrict__ vW2, const float* __restrict__ vb2,
    const int*   __restrict__ batch)
{
    __shared__ float2 xb[F * TA];            // broadcast-packed activations, 32KB
    __shared__ float  wq_s[CHUNK * F];       // 4KB
    __shared__ float  wv_s[CHUNK * F];       // 4KB
    __shared__ float  red[4][4][8][3];       // [warp][ag][atom][comp]

    const int tid = threadIdx.x;
    const int hg = tid >> 2;       // 0..31
    const int ag = tid & 3;        // 0..3
    const int lane = tid & 31;
    const int wrp = tid >> 5;
    const int base = blockIdx.x * TA;

    // load h0 tile, broadcast-packed (x,x)
    for (int idx = tid; idx < TA * F; idx += 128) {
        int a = idx >> 7;          // atom 0..31
        int k = idx & (F - 1);
        float x = h0[(base + a) * F + k];
        xb[k * TA + a] = make_float2(x, x);
    }

    u64 accq[2][8], accv[2][8];
#pragma unroll
    for (int p = 0; p < 2; p++)
#pragma unroll
        for (int i = 0; i < 8; i++) { accq[p][i] = 0ull; accv[p][i] = 0ull; }

    for (int c = 0; c < F / CHUNK; c++) {
        __syncthreads();
        // stage CHUNK rows of both weight matrices
        const float4* qs = (const float4*)(qW1 + c * CHUNK * F);
        const float4* vs = (const float4*)(vW1 + c * CHUNK * F);
        float4* qd = (float4*)wq_s;
        float4* vd = (float4*)wv_s;
        qd[tid] = qs[tid]; qd[tid + 128] = qs[tid + 128];
        vd[tid] = vs[tid]; vd[tid + 128] = vs[tid + 128];
        __syncthreads();

#pragma unroll
        for (int r = 0; r < CHUNK; r++) {
            const int k = c * CHUNK + r;
            F4U wq; wq.f = *(const float4*)&wq_s[r * F + hg * 4];
            F4U wv; wv.f = *(const float4*)&wv_s[r * F + hg * 4];
            const ulonglong2* xp = (const ulonglong2*)&xb[k * TA + ag * 8];
#pragma unroll
            for (int ii = 0; ii < 4; ii++) {
                ulonglong2 x2 = xp[ii];
                FMA2(accq[0][2 * ii],     wq.u[0], x2.x);
                FMA2(accq[1][2 * ii],     wq.u[1], x2.x);
                FMA2(accq[0][2 * ii + 1], wq.u[0], x2.y);
                FMA2(accq[1][2 * ii + 1], wq.u[1], x2.y);
                FMA2(accv[0][2 * ii],     wv.u[0], x2.x);
                FMA2(accv[1][2 * ii],     wv.u[1], x2.x);
                FMA2(accv[0][2 * ii + 1], wv.u[0], x2.y);
                FMA2(accv[1][2 * ii + 1], wv.u[1], x2.y);
            }
        }
    }

    // per-thread head params for its 4 hidden units
    float qb[4], qw2[4], vb[4], vw0[4], vw1[4];
#pragma unroll
    for (int h = 0; h < 4; h++) {
        int hh = hg * 4 + h;
        qb[h]  = qb1[hh];
        qw2[h] = qW2[hh];
        vb[h]  = vb1[hh];
        vw0[h] = vW2[2 * hh + 0];
        vw1[h] = vW2[2 * hh + 1];
    }

    // epilogue: activation + layer-2 partials, reduce over hidden groups
#pragma unroll
    for (int i = 0; i < 8; i++) {
        float sq = 0.f, sv0 = 0.f, sv1 = 0.f;
#pragma unroll
        for (int hp = 0; hp < 2; hp++) {
            float a0, a1; unpack2(accq[hp][i], a0, a1);
            sq += siluf(a0 + qb[2 * hp])     * qw2[2 * hp]
                + siluf(a1 + qb[2 * hp + 1]) * qw2[2 * hp + 1];
            float b0, b1; unpack2(accv[hp][i], b0, b1);
            float s0 = siluf(b0 + vb[2 * hp]);
            float s1 = siluf(b1 + vb[2 * hp + 1]);
            sv0 += s0 * vw0[2 * hp] + s1 * vw0[2 * hp + 1];
            sv1 += s0 * vw1[2 * hp] + s1 * vw1[2 * hp + 1];
        }
        // reduce over the 8 hidden-groups in this warp (stride 4 in lane space)
#pragma unroll
        for (int m = 16; m >= 4; m >>= 1) {
            sq  += __shfl_xor_sync(0xFFFFFFFFu, sq,  m);
            sv0 += __shfl_xor_sync(0xFFFFFFFFu, sv0, m);
            sv1 += __shfl_xor_sync(0xFFFFFFFFu, sv1, m);
        }
        if (lane < 4) {
            red[wrp][lane][i][0] = sq;
            red[wrp][lane][i][1] = sv0;
            red[wrp][lane][i][2] = sv1;
        }
    }
    __syncthreads();

    // finish: 96 threads, one (atom, component) each
    int comp = tid & 3;
    if (comp < 3) {
        int al  = tid >> 2;        // local atom 0..31
        int ag2 = al >> 3, i2 = al & 7;
        float s = red[0][ag2][i2][comp] + red[1][ag2][i2][comp]
                + red[2][ag2][i2][comp] + red[3][ag2][i2][comp];
        int gi = base + al;
        if (comp == 0) {
            g_q[gi] = s;
            atomicAdd(&g_qsum[batch[gi]], s);
        } else if (comp == 1) {
            float c6 = softplusf(s + vb2[0]);
            g_sc6[gi] = sqrtf(c6);
        } else {
            float rv = softplusf(s + vb2[1]);
            g_r3[gi] = rv * rv * rv;
        }
    }
}

// ---------------- K2: segment starts (binary search) + per-graph mean ----------------
__global__ void seg_kernel(const int* __restrict__ batch, int N) {
    __shared__ int ss[G + 1];
    int t = threadIdx.x;
    if (t <= G) {
        int lo = 0, hi = N;
        while (lo < hi) { int m = (lo + hi) >> 1; if (batch[m] < t) lo = m + 1; else hi = m; }
        ss[t] = lo;
    }
    __syncthreads();
    if (t < G) {
        int c = ss[t + 1] - ss[t];
        g_start[t] = ss[t];
        g_cnt[t]   = c;
        g_qmean[t] = g_qsum[t] / fmaxf((float)c, 1.0f);
    }
}

// ---------------- K3: pairwise (symmetric, smem-cached per graph) ----------------
__global__ __launch_bounds__(256) void pair_kernel(
    const float* __restrict__ pos,
    const float* __restrict__ sigma)
{
    __shared__ float sx[MAXC], sy[MAXC], sz[MAXC];
    __shared__ float sq[MAXC], sc[MAXC], sr[MAXC];
    __shared__ float sred[8];

    const int g  = blockIdx.x / SPLIT;
    const int sp = blockIdx.x % SPLIT;
    const int tid = threadIdx.x;
    const int s = g_start[g];
    const int c = g_cnt[g];
    const float qm = g_qmean[g];

    for (int t = tid; t < c; t += 256) {
        int j = s + t;
        sx[t] = pos[3 * j + 0];
        sy[t] = pos[3 * j + 1];
        sz[t] = pos[3 * j + 2];
        sq[t] = g_q[j] - qm;
        sc[t] = g_sc6[j];
        sr[t] = g_r3[j];
    }
    __syncthreads();

    const float invs = 1.0f / (1.41421356f * sigma[0]);
    const int wg   = (tid >> 5) + sp * 8;   // 0..23 global warp within graph
    const int lane = tid & 31;

    float eel = 0.f, evd = 0.f;
    for (int i = wg; i < c; i += SPLIT * 8) {
        float px = sx[i], py = sy[i], pz = sz[i];
        float qi = sq[i], c6i = sc[i], r3i = sr[i];
        for (int j = i + 1 + lane; j < c; j += 32) {
            float dx = px - sx[j];
            float dy = py - sy[j];
            float dz = pz - sz[j];
            float dsq = dx * dx + dy * dy + dz * dz;
            float dist = sqrtf(dsq + 1e-8f);
            eel += qi * sq[j] * erff(dist * invs) / (dist + 1e-8f);
            float damp = dsq * dsq * dsq + r3i * sr[j];
            evd -= c6i * sc[j] / (damp + 1e-8f);
        }
    }

    // each unordered pair accounts for both ordered terms (2 * 0.5 = 1)
    float tot = KE_CONST * eel + evd;
#pragma unroll
    for (int o = 16; o > 0; o >>= 1)
        tot += __shfl_down_sync(0xFFFFFFFFu, tot, o);
    if (lane == 0) sred[tid >> 5] = tot;
    __syncthreads();
    if (tid == 0) {
        float t = 0.f;
        for (int w = 0; w < 8; w++) t += sred[w];
        g_partial[blockIdx.x] = (double)t;
    }
}

// ---------------- K4: final reduction ----------------
__global__ void finish_kernel(float* __restrict__ out) {
    __shared__ double sred[8];
    double acc = 0.0;
    for (int idx = threadIdx.x; idx < G * SPLIT; idx += blockDim.x)
        acc += g_partial[idx];
#pragma unroll
    for (int o = 16; o > 0; o >>= 1)
        acc += __shfl_down_sync(0xFFFFFFFFu, acc, o);
    int lane = threadIdx.x & 31, warp = threadIdx.x >> 5;
    if (lane == 0) sred[warp] = acc;
    __syncthreads();
    if (threadIdx.x == 0) {
        double t = 0.0;
        int nw = (blockDim.x + 31) >> 5;
        for (int w = 0; w < nw; w++) t += sred[w];
        out[0] = (float)t;
    }
}

// ---------------- launch ----------------
extern "C" void kernel_launch(void* const* d_in, const int* in_sizes, int n_in,
                              void* d_out, int out_size) {
    const float* h0    = (const float*)d_in[0];
    const float* pos   = (const float*)d_in[2];
    const float* qW1   = (const float*)d_in[3];
    const float* qb1   = (const float*)d_in[4];
    const float* qW2   = (const float*)d_in[5];
    const float* sigma = (const float*)d_in[6];
    const float* vW1   = (const float*)d_in[7];
    const float* vb1   = (const float*)d_in[8];
    const float* vW2   = (const float*)d_in[9];
    const float* vb2   = (const float*)d_in[10];
    const int*   batch = (const int*)d_in[11];

    const int N = in_sizes[0] / F;   // 6144

    zero_kernel<<<1, 64>>>();
    mlp_kernel<<<N / TA, 128>>>(h0, qW1, qb1, qW2, vW1, vb1, vW2, vb2, batch);
    seg_kernel<<<1, 64>>>(batch, N);
    pair_kernel<<<G * SPLIT, 256>>>(pos, sigma);
    finish_kernel<<<1, 256>>>((float*)d_out);
}

// round 4
// speedup vs baseline: 1.4833x; 1.3890x over previous
#include <cuda_runtime.h>
#include <cuda_bf16.h>

#define NATOMS 6144
#define F 128
#define G 48
#define MT 32            // GEMM M tile
#define KC 16            // GEMM K chunk
#define MTILES (NATOMS / MT)   // 192
#define SPLIT 6          // pair blocks per graph
#define MAXC 256         // max atoms per graph (mean ~128)
#define KE_CONST 14.3996f

typedef unsigned long long u64;

// ---------------- scratch ----------------
__device__ float    g_q[NATOMS];
__device__ float    g_sc6[NATOMS];
__device__ float    g_r3[NATOMS];
__device__ int      g_start[G];
__device__ int      g_cnt[G];
__device__ double   g_esum;
__device__ unsigned g_done;

__device__ __forceinline__ float softplusf(float x) {
    return fmaxf(x, 0.0f) + log1pf(expf(-fabsf(x)));
}
__device__ __forceinline__ float siluf(float x) {
    return x / (1.0f + expf(-x));
}

// packed double-rate fp32 FMA (sm_100+)
#define FMA2(acc, w, x) asm("fma.rn.f32x2 %0, %1, %2, %0;" : "+l"(acc) : "l"(w), "l"(x))

__device__ __forceinline__ u64 bcast2(float x) {
    u64 r; asm("mov.b64 %0, {%1,%1};" : "=l"(r) : "f"(x)); return r;
}
__device__ __forceinline__ void unpack2(u64 p, float &lo, float &hi) {
    asm("mov.b64 {%0,%1}, %2;" : "=f"(lo), "=f"(hi) : "l"(p));
}

// ================= K1: fused MLP GEMM =================
// grid = 2*MTILES + 1.  bid < 2*MTILES: GEMM block (head = bid/MTILES,
// m-tile = bid%MTILES).  bid == 2*MTILES: seg/zero service block.
// 128 threads: ng = tid&15 (8 n-cols each), mg = tid>>4 (4 m-rows each).
__global__ __launch_bounds__(128) void mlp_gemm_kernel(
    const float* __restrict__ h0,
    const float* __restrict__ qW1, const float* __restrict__ qb1,
    const float* __restrict__ qW2,
    const float* __restrict__ vW1, const float* __restrict__ vb1,
    const float* __restrict__ vW2, const float* __restrict__ vb2,
    const int*   __restrict__ batch)
{
    const int bid = blockIdx.x;
    const int tid = threadIdx.x;

    if (bid == 2 * MTILES) {
        // service block: zero accumulators + segment bounds via binary search
        if (tid == 0) { g_esum = 0.0; g_done = 0u; }
        __shared__ int ss[G + 1];
        if (tid <= G) {
            int lo = 0, hi = NATOMS;
            while (lo < hi) {
                int m = (lo + hi) >> 1;
                if (batch[m] < tid) lo = m + 1; else hi = m;
            }
            ss[tid] = lo;
        }
        __syncthreads();
        if (tid < G) { g_start[tid] = ss[tid]; g_cnt[tid] = ss[tid + 1] - ss[tid]; }
        return;
    }

    const int head  = bid / MTILES;          // 0 = charge, 1 = vdw
    const int mbase = (bid % MTILES) * MT;
    const int ng = tid & 15;
    const int mg = tid >> 4;

    const float* __restrict__ W1 = head ? vW1 : qW1;
    const float* __restrict__ B1 = head ? vb1 : qb1;

    __shared__ float As[MT][20];       // [m][k], padded
    __shared__ float Bs[KC][F];        // [k][n]

    u64 acc[4][4];
#pragma unroll
    for (int i = 0; i < 4; i++)
#pragma unroll
        for (int j = 0; j < 4; j++) acc[i][j] = 0ull;

    const int am = tid >> 2;           // A load: m row 0..31
    const int ak = (tid & 3) * 4;      // A load: 4 k values
    const int br = tid >> 3;           // B load: k row 0..15
    const int bc = (tid & 7) * 16;     // B load: 16 n cols

    for (int c = 0; c < F / KC; c++) {
        // stage A: h0[mbase+am][c*16+ak .. +3]
        float4 av = *(const float4*)&h0[(mbase + am) * F + c * KC + ak];
        // stage B: W1[c*16+br][bc .. bc+15]
        float4 bv0 = *(const float4*)&W1[(c * KC + br) * F + bc + 0];
        float4 bv1 = *(const float4*)&W1[(c * KC + br) * F + bc + 4];
        float4 bv2 = *(const float4*)&W1[(c * KC + br) * F + bc + 8];
        float4 bv3 = *(const float4*)&W1[(c * KC + br) * F + bc + 12];
        __syncthreads();
        *(float4*)&As[am][ak] = av;
        *(float4*)&Bs[br][bc + 0]  = bv0;
        *(float4*)&Bs[br][bc + 4]  = bv1;
        *(float4*)&Bs[br][bc + 8]  = bv2;
        *(float4*)&Bs[br][bc + 12] = bv3;
        __syncthreads();

#pragma unroll
        for (int r = 0; r < KC; r++) {
            u64 a0 = bcast2(As[mg * 4 + 0][r]);
            u64 a1 = bcast2(As[mg * 4 + 1][r]);
            u64 a2 = bcast2(As[mg * 4 + 2][r]);
            u64 a3 = bcast2(As[mg * 4 + 3][r]);
            ulonglong2 b01 = *(const ulonglong2*)&Bs[r][ng * 8 + 0];
            ulonglong2 b23 = *(const ulonglong2*)&Bs[r][ng * 8 + 4];
            FMA2(acc[0][0], b01.x, a0); FMA2(acc[0][1], b01.y, a0);
            FMA2(acc[0][2], b23.x, a0); FMA2(acc[0][3], b23.y, a0);
            FMA2(acc[1][0], b01.x, a1); FMA2(acc[1][1], b01.y, a1);
            FMA2(acc[1][2], b23.x, a1); FMA2(acc[1][3], b23.y, a1);
            FMA2(acc[2][0], b01.x, a2); FMA2(acc[2][1], b01.y, a2);
            FMA2(acc[2][2], b23.x, a2); FMA2(acc[2][3], b23.y, a2);
            FMA2(acc[3][0], b01.x, a3); FMA2(acc[3][1], b01.y, a3);
            FMA2(acc[3][2], b23.x, a3); FMA2(acc[3][3], b23.y, a3);
        }
    }

    // ---- fused second layer: silu + dot(w2) + reduce over ng lanes ----
    const int n0 = ng * 8;
    float b1v[8], w2a[8], w2b[8];
#pragma unroll
    for (int j = 0; j < 8; j++) {
        b1v[j] = B1[n0 + j];
        if (head) { w2a[j] = vW2[2 * (n0 + j)]; w2b[j] = vW2[2 * (n0 + j) + 1]; }
        else      { w2a[j] = qW2[n0 + j];       w2b[j] = 0.0f; }
    }

#pragma unroll
    for (int i = 0; i < 4; i++) {
        float s0 = 0.f, s1 = 0.f;
#pragma unroll
        for (int j = 0; j < 4; j++) {
            float c0, c1; unpack2(acc[i][j], c0, c1);
            float h0v = siluf(c0 + b1v[2 * j]);
            float h1v = siluf(c1 + b1v[2 * j + 1]);
            s0 += h0v * w2a[2 * j] + h1v * w2a[2 * j + 1];
            s1 += h0v * w2b[2 * j] + h1v * w2b[2 * j + 1];
        }
#pragma unroll
        for (int m = 8; m >= 1; m >>= 1) {
            s0 += __shfl_xor_sync(0xFFFFFFFFu, s0, m);
            s1 += __shfl_xor_sync(0xFFFFFFFFu, s1, m);
        }
        if (ng == 0) {
            int atom = mbase + mg * 4 + i;
            if (head == 0) {
                g_q[atom] = s0;
            } else {
                float c6 = softplusf(s0 + vb2[0]);
                float rv = softplusf(s1 + vb2[1]);
                g_sc6[atom] = sqrtf(c6);
                g_r3[atom]  = rv * rv * rv;
            }
        }
    }
}

// ================= K2: pairwise + full reduction =================
// grid = G*SPLIT, 128 threads.  Each block serves graph g = bid/SPLIT,
// warp-per-row strided across SPLIT*4 warps.  Mean computed in-block.
__global__ __launch_bounds__(128) void pair_kernel(
    const float* __restrict__ pos,
    const float* __restrict__ sigma,
    float* __restrict__ out)
{
    __shared__ float sx[MAXC], sy[MAXC], sz[MAXC];
    __shared__ float sq[MAXC], sc[MAXC], sr[MAXC];
    __shared__ float wred[4];
    __shared__ float s_qm;

    const int bid = blockIdx.x;
    const int g  = bid / SPLIT;
    const int sp = bid % SPLIT;
    const int tid = threadIdx.x;
    const int lane = tid & 31;
    const int wrp  = tid >> 5;

    const int s = g_start[g];
    const int c = g_cnt[g];

    float qacc = 0.f;
    for (int t = tid; t < c; t += 128) {
        int j = s + t;
        sx[t] = pos[3 * j + 0];
        sy[t] = pos[3 * j + 1];
        sz[t] = pos[3 * j + 2];
        float qv = g_q[j];
        sq[t] = qv;  qacc += qv;
        sc[t] = g_sc6[j];
        sr[t] = g_r3[j];
    }
    // block-wide mean of q
#pragma unroll
    for (int o = 16; o > 0; o >>= 1) qacc += __shfl_xor_sync(0xFFFFFFFFu, qacc, o);
    if (lane == 0) wred[wrp] = qacc;
    __syncthreads();
    if (tid == 0) s_qm = (wred[0] + wred[1] + wred[2] + wred[3]) / fmaxf((float)c, 1.0f);
    __syncthreads();
    const float qm = s_qm;
    for (int t = tid; t < c; t += 128) sq[t] -= qm;
    __syncthreads();

    const float invs = 1.0f / (1.41421356f * sigma[0]);
    const int wg = wrp + sp * 4;            // 0 .. SPLIT*4-1

    float eel = 0.f, evd = 0.f;
    for (int i = wg; i < c; i += SPLIT * 4) {
        float px = sx[i], py = sy[i], pz = sz[i];
        float qi = sq[i], c6i = sc[i], r3i = sr[i];
        for (int j = i + 1 + lane; j < c; j += 32) {
            float dx = px - sx[j];
            float dy = py - sy[j];
            float dz = pz - sz[j];
            float dsq = dx * dx + dy * dy + dz * dz;
            float dist = sqrtf(dsq + 1e-8f);
            eel += qi * sq[j] * __fdividef(erff(dist * invs), dist + 1e-8f);
            float damp = dsq * dsq * dsq + r3i * sr[j];
            evd -= __fdividef(c6i * sc[j], damp + 1e-8f);
        }
    }

    float tot = KE_CONST * eel + evd;   // unordered pairs: 2 * 0.5 = 1
#pragma unroll
    for (int o = 16; o > 0; o >>= 1) tot += __shfl_down_sync(0xFFFFFFFFu, tot, o);
    if (lane == 0) wred[wrp] = tot;
    __syncthreads();
    if (tid == 0) {
        double bsum = (double)(wred[0] + wred[1] + wred[2] + wred[3]);
        atomicAdd(&g_esum, bsum);
        __threadfence();
        unsigned t = atomicAdd(&g_done, 1u);
        if (t == gridDim.x - 1) {
            g_done = 0u;
            double total = atomicAdd(&g_esum, 0.0);   // coherent read
            out[0] = (float)total;
        }
    }
}

// ---------------- launch ----------------
extern "C" void kernel_launch(void* const* d_in, const int* in_sizes, int n_in,
                              void* d_out, int out_size) {
    const float* h0    = (const float*)d_in[0];
    const float* pos   = (const float*)d_in[2];
    const float* qW1   = (const float*)d_in[3];
    const float* qb1   = (const float*)d_in[4];
    const float* qW2   = (const float*)d_in[5];
    const float* sigma = (const float*)d_in[6];
    const float* vW1   = (const float*)d_in[7];
    const float* vb1   = (const float*)d_in[8];
    const float* vW2   = (const float*)d_in[9];
    const float* vb2   = (const float*)d_in[10];
    const int*   batch = (const int*)d_in[11];

    mlp_gemm_kernel<<<2 * MTILES + 1, 128>>>(h0, qW1, qb1, qW2,
                                             vW1, vb1, vW2, vb2, batch);
    pair_kernel<<<G * SPLIT, 128>>>(pos, sigma, (float*)d_out);
}

// round 5
// speedup vs baseline: 1.5414x; 1.0392x over previous
#include <cuda_runtime.h>
#include <cuda_bf16.h>

#define NATOMS 6144
#define F 128
#define G 48
#define MT 32                  // GEMM M tile
#define KC 16                  // GEMM K chunk
#define MTILES (NATOMS / MT)   // 192
#define SPLIT 12               // pair blocks per graph
#define MAXC 256
#define KE_CONST 14.3996f

typedef unsigned long long u64;

// ---------------- scratch ----------------
__device__ float    g_q[NATOMS];
__device__ float    g_sc6[NATOMS];
__device__ float    g_r3[NATOMS];
__device__ int      g_start[G];
__device__ int      g_cnt[G];
__device__ double   g_esum;
__device__ unsigned g_done;

__device__ __forceinline__ float softplusf(float x) {
    return fmaxf(x, 0.0f) + log1pf(expf(-fabsf(x)));
}
__device__ __forceinline__ float siluf(float x) {
    return x / (1.0f + expf(-x));
}

// packed double-rate fp32 FMA (sm_100+)
#define FMA2(acc, w, x) asm("fma.rn.f32x2 %0, %1, %2, %0;" : "+l"(acc) : "l"(w), "l"(x))

__device__ __forceinline__ void unpack2(u64 p, float &lo, float &hi) {
    asm("mov.b64 {%0,%1}, %2;" : "=f"(lo), "=f"(hi) : "l"(p));
}

__device__ __forceinline__ unsigned smem_u32(const void* p) {
    return (unsigned)__cvta_generic_to_shared(p);
}
__device__ __forceinline__ void cp16(unsigned dst, const void* src) {
    asm volatile("cp.async.ca.shared.global [%0], [%1], 16;\n" :: "r"(dst), "l"(src));
}
#define CP_COMMIT() asm volatile("cp.async.commit_group;\n" ::: "memory")
#define CP_WAIT0()  asm volatile("cp.async.wait_group 0;\n" ::: "memory")

// ================= K1: fused MLP GEMM (double-buffered) =================
// grid = 2*MTILES + 1.  bid < 2*MTILES: GEMM block (head = bid/MTILES,
// m-tile = bid%MTILES).  Last block: segment bounds + accumulator reset.
// 128 threads: ng = tid&15 (8 n-cols), mg = tid>>4 (4 m-rows).
__global__ __launch_bounds__(128) void mlp_gemm_kernel(
    const float* __restrict__ h0,
    const float* __restrict__ qW1, const float* __restrict__ qb1,
    const float* __restrict__ qW2,
    const float* __restrict__ vW1, const float* __restrict__ vb1,
    const float* __restrict__ vW2, const float* __restrict__ vb2,
    const int*   __restrict__ batch)
{
    const int bid = blockIdx.x;
    const int tid = threadIdx.x;

    if (bid == 2 * MTILES) {
        if (tid == 0) { g_esum = 0.0; g_done = 0u; }
        __shared__ int ss[G + 1];
        if (tid <= G) {
            int lo = 0, hi = NATOMS;
            while (lo < hi) {
                int m = (lo + hi) >> 1;
                if (batch[m] < tid) lo = m + 1; else hi = m;
            }
            ss[tid] = lo;
        }
        __syncthreads();
        if (tid < G) { g_start[tid] = ss[tid]; g_cnt[tid] = ss[tid + 1] - ss[tid]; }
        return;
    }

    const int head  = bid / MTILES;          // 0 = charge, 1 = vdw
    const int mbase = (bid % MTILES) * MT;
    const int ng = tid & 15;
    const int mg = tid >> 4;

    const float* __restrict__ W1 = head ? vW1 : qW1;
    const float* __restrict__ B1 = head ? vb1 : qb1;

    // A broadcast-packed: As[buf][k][m] float2, padded row stride 33
    __shared__ float2 As[2][KC][33];
    __shared__ float  Bs[2][KC][F];

    u64 acc[4][4];
#pragma unroll
    for (int i = 0; i < 4; i++)
#pragma unroll
        for (int j = 0; j < 4; j++) acc[i][j] = 0ull;

    const int am = tid >> 2;           // A: m row 0..31
    const int ak = (tid & 3) * 4;      // A: 4 k values

    // prologue: chunk 0
    float4 av = *(const float4*)&h0[(mbase + am) * F + ak];
#pragma unroll
    for (int i = 0; i < 4; i++)
        cp16(smem_u32(&Bs[0][0][0]) + (i * 128 + tid) * 16,
             (const char*)(W1) + (i * 128 + tid) * 16);
    CP_COMMIT();

    for (int c = 0; c < F / KC; c++) {
        const int buf = c & 1;
        // pack A chunk c into smem (x,x)
        As[buf][ak + 0][am] = make_float2(av.x, av.x);
        As[buf][ak + 1][am] = make_float2(av.y, av.y);
        As[buf][ak + 2][am] = make_float2(av.z, av.z);
        As[buf][ak + 3][am] = make_float2(av.w, av.w);
        CP_WAIT0();
        __syncthreads();
        if (c < F / KC - 1) {
            av = *(const float4*)&h0[(mbase + am) * F + (c + 1) * KC + ak];
            const char* src = (const char*)(W1 + (c + 1) * KC * F);
            unsigned dst = smem_u32(&Bs[buf ^ 1][0][0]);
#pragma unroll
            for (int i = 0; i < 4; i++)
                cp16(dst + (i * 128 + tid) * 16, src + (i * 128 + tid) * 16);
            CP_COMMIT();
        }

#pragma unroll
        for (int r = 0; r < KC; r++) {
            u64 a0 = *(const u64*)&As[buf][r][mg * 4 + 0];
            u64 a1 = *(const u64*)&As[buf][r][mg * 4 + 1];
            u64 a2 = *(const u64*)&As[buf][r][mg * 4 + 2];
            u64 a3 = *(const u64*)&As[buf][r][mg * 4 + 3];
            ulonglong2 b01 = *(const ulonglong2*)&Bs[buf][r][ng * 8 + 0];
            ulonglong2 b23 = *(const ulonglong2*)&Bs[buf][r][ng * 8 + 4];
            FMA2(acc[0][0], b01.x, a0); FMA2(acc[0][1], b01.y, a0);
            FMA2(acc[0][2], b23.x, a0); FMA2(acc[0][3], b23.y, a0);
            FMA2(acc[1][0], b01.x, a1); FMA2(acc[1][1], b01.y, a1);
            FMA2(acc[1][2], b23.x, a1); FMA2(acc[1][3], b23.y, a1);
            FMA2(acc[2][0], b01.x, a2); FMA2(acc[2][1], b01.y, a2);
            FMA2(acc[2][2], b23.x, a2); FMA2(acc[2][3], b23.y, a2);
            FMA2(acc[3][0], b01.x, a3); FMA2(acc[3][1], b01.y, a3);
            FMA2(acc[3][2], b23.x, a3); FMA2(acc[3][3], b23.y, a3);
        }
        __syncthreads();
    }

    // ---- fused second layer: silu + dot(w2) + reduce over ng lanes ----
    const int n0 = ng * 8;
    float b1v[8], w2a[8], w2b[8];
#pragma unroll
    for (int j = 0; j < 8; j++) {
        b1v[j] = B1[n0 + j];
        if (head) { w2a[j] = vW2[2 * (n0 + j)]; w2b[j] = vW2[2 * (n0 + j) + 1]; }
        else      { w2a[j] = qW2[n0 + j];       w2b[j] = 0.0f; }
    }

#pragma unroll
    for (int i = 0; i < 4; i++) {
        float s0 = 0.f, s1 = 0.f;
#pragma unroll
        for (int j = 0; j < 4; j++) {
            float c0, c1; unpack2(acc[i][j], c0, c1);
            float h0v = siluf(c0 + b1v[2 * j]);
            float h1v = siluf(c1 + b1v[2 * j + 1]);
            s0 += h0v * w2a[2 * j] + h1v * w2a[2 * j + 1];
            s1 += h0v * w2b[2 * j] + h1v * w2b[2 * j + 1];
        }
#pragma unroll
        for (int m = 8; m >= 1; m >>= 1) {
            s0 += __shfl_xor_sync(0xFFFFFFFFu, s0, m);
            s1 += __shfl_xor_sync(0xFFFFFFFFu, s1, m);
        }
        if (ng == 0) {
            int atom = mbase + mg * 4 + i;
            if (head == 0) {
                g_q[atom] = s0;
            } else {
                float c6 = softplusf(s0 + vb2[0]);
                float rv = softplusf(s1 + vb2[1]);
                g_sc6[atom] = sqrtf(c6);
                g_r3[atom]  = rv * rv * rv;
            }
        }
    }
}

// ================= K2: pairwise + full reduction =================
__global__ __launch_bounds__(128) void pair_kernel(
    const float* __restrict__ pos,
    const float* __restrict__ sigma,
    float* __restrict__ out)
{
    __shared__ float sx[MAXC], sy[MAXC], sz[MAXC];
    __shared__ float sq[MAXC], sc[MAXC], sr[MAXC];
    __shared__ float wred[4];
    __shared__ float s_qm;

    const int bid = blockIdx.x;
    const int g  = bid / SPLIT;
    const int sp = bid % SPLIT;
    const int tid = threadIdx.x;
    const int lane = tid & 31;
    const int wrp  = tid >> 5;

    const int s = g_start[g];
    const int c = g_cnt[g];

    float qacc = 0.f;
    for (int t = tid; t < c; t += 128) {
        int j = s + t;
        sx[t] = pos[3 * j + 0];
        sy[t] = pos[3 * j + 1];
        sz[t] = pos[3 * j + 2];
        float qv = g_q[j];
        sq[t] = qv;  qacc += qv;
        sc[t] = g_sc6[j];
        sr[t] = g_r3[j];
    }
#pragma unroll
    for (int o = 16; o > 0; o >>= 1) qacc += __shfl_xor_sync(0xFFFFFFFFu, qacc, o);
    if (lane == 0) wred[wrp] = qacc;
    __syncthreads();
    if (tid == 0) s_qm = (wred[0] + wred[1] + wred[2] + wred[3]) / fmaxf((float)c, 1.0f);
    __syncthreads();
    const float qm = s_qm;
    for (int t = tid; t < c; t += 128) sq[t] -= qm;
    __syncthreads();

    const float invs = 1.0f / (1.41421356f * sigma[0]);
    const int wg = wrp + sp * 4;            // 0 .. SPLIT*4-1

    float eel = 0.f, evd = 0.f;
    for (int i = wg; i < c; i += SPLIT * 4) {
        float px = sx[i], py = sy[i], pz = sz[i];
        float qi = sq[i], c6i = sc[i], r3i = sr[i];
        for (int j = i + 1 + lane; j < c; j += 32) {
            float dx = px - sx[j];
            float dy = py - sy[j];
            float dz = pz - sz[j];
            float dsq = dx * dx + dy * dy + dz * dz;
            float dist = sqrtf(dsq + 1e-8f);
            eel += qi * sq[j] * __fdividef(erff(dist * invs), dist + 1e-8f);
            float damp = dsq * dsq * dsq + r3i * sr[j];
            evd -= __fdividef(c6i * sc[j], damp + 1e-8f);
        }
    }

    float tot = KE_CONST * eel + evd;   // unordered pairs: 2 * 0.5 = 1
#pragma unroll
    for (int o = 16; o > 0; o >>= 1) tot += __shfl_down_sync(0xFFFFFFFFu, tot, o);
    if (lane == 0) wred[wrp] = tot;
    __syncthreads();
    if (tid == 0) {
        double bsum = (double)(wred[0] + wred[1] + wred[2] + wred[3]);
        atomicAdd(&g_esum, bsum);
        __threadfence();
        unsigned t = atomicAdd(&g_done, 1u);
        if (t == gridDim.x - 1) {
            g_done = 0u;
            double total = atomicAdd(&g_esum, 0.0);   // coherent read
            out[0] = (float)total;
        }
    }
}

// ---------------- launch ----------------
extern "C" void kernel_launch(void* const* d_in, const int* in_sizes, int n_in,
                              void* d_out, int out_size) {
    const float* h0    = (const float*)d_in[0];
    const float* pos   = (const float*)d_in[2];
    const float* qW1   = (const float*)d_in[3];
    const float* qb1   = (const float*)d_in[4];
    const float* qW2   = (const float*)d_in[5];
    const float* sigma = (const float*)d_in[6];
    const float* vW1   = (const float*)d_in[7];
    const float* vb1   = (const float*)d_in[8];
    const float* vW2   = (const float*)d_in[9];
    const float* vb2   = (const float*)d_in[10];
    const int*   batch = (const int*)d_in[11];

    mlp_gemm_kernel<<<2 * MTILES + 1, 128>>>(h0, qW1, qb1, qW2,
                                             vW1, vb1, vW2, vb2, batch);
    pair_kernel<<<G * SPLIT, 128>>>(pos, sigma, (float*)d_out);
}